// round 10
// baseline (speedup 1.0000x reference)
#include <cuda_runtime.h>
#include <cuda_bf16.h>
#include <math.h>

// B=16384 samples, L=256 latents, H=16 hidden.
// out[b,l] = sigmoid( sum_h W2[l,h]*softplus(y[b,l]*W1[l,h]+b1[l,h]) + b2[l] )
//
// Kernel 1 (tiny): tabulate {g_l(y_pt), h*g_l'(y_pt)} at 17 grid points.
// Kernel 2 (PDL secondary): prefetch y, griddepcontrol.wait, assemble cubic
// coefficients into swizzled smem, stream y->out with conflict-free LDS.128.

#define LATENTS 256
#define HID     16
#define NINT    16
#define NPTS    (NINT + 1)
#define Y_LO    (-6.5f)
#define STEP_F  (13.0f / (float)NINT)
#define INVH_F  ((float)NINT / 13.0f)
#define OFF_F   8.0f                       // -Y_LO * INVH

#define EV_GRID  296
#define EV_BLK   1024
#define TAB_F4   (NINT * LATENTS)          // 4096 float4 = 65536 B

// Point table {f, h*f'} in device global scratch (allocation-free).
__device__ float2 g_pts[NPTS * LATENTS];

// ---------------------------------------------------------------------------
// Build: one thread per (pt, latent). 17 blocks x 256 threads, MUFU intrinsics.
// ---------------------------------------------------------------------------
__global__ void build_pts_kernel(const float* __restrict__ W1,
                                 const float* __restrict__ b1,
                                 const float* __restrict__ W2,
                                 const float* __restrict__ b2)
{
    const int l  = threadIdx.x;            // 0..255
    const int pt = blockIdx.x;             // 0..16
    const float y0 = Y_LO + STEP_F * (float)pt;

    float a  = b2[l];
    float da = 0.0f;
#pragma unroll
    for (int h = 0; h < HID; ++h) {
        const float w1 = W1[l * HID + h];
        const float bb = b1[l * HID + h];
        const float w2 = W2[l * HID + h];
        const float x  = fmaf(y0, w1, bb);
        const float e  = __expf(-fabsf(x));                  // exp(-|x|) <= 1
        const float iv = __fdividef(1.0f, 1.0f + e);
        const float sp = fmaxf(x, 0.0f) + __logf(1.0f + e);  // softplus(x)
        const float s  = (x >= 0.0f) ? iv : e * iv;          // sigmoid(x)
        a  = fmaf(w2, sp, a);
        da = fmaf(w2 * s, w1, da);
    }
    const float eo = __expf(-a);
    const float g  = __fdividef(1.0f, 1.0f + eo);
    g_pts[pt * LATENTS + l] = make_float2(g, STEP_F * (g * (1.0f - g) * da));
}

// ---------------------------------------------------------------------------
// Eval (PDL secondary): 296 CTAs x 1024 threads, 64KB smem (2 CTAs/SM).
// Smem layout swizzled: tab[iv*256 + (l&3)*64 + (l>>2)].
// Thread handles latents l = 4*lg+j (lg = gtid & 63); per-j LDS.128 is
// stride-16B across lanes (conflict-free); iv adds multiples of 4096B.
// ---------------------------------------------------------------------------
__device__ __forceinline__ float interp1(float yv, const float4* __restrict__ col)
{
    float t = fmaf(yv, INVH_F, OFF_F);
    t = fminf(fmaxf(t, 0.0f), (float)NINT - 5e-4f);
    const int   i = (int)t;
    const float u = t - (float)i;
    const float4 c = col[i * LATENTS];     // stride 4096B per interval
    return fmaf(fmaf(fmaf(c.w, u, c.z), u, c.y), u, c.x);
}

__global__ __launch_bounds__(EV_BLK, 2)
void eval_vec_kernel(const float4* __restrict__ y4,
                     float4* __restrict__ out4,
                     int n4)
{
    extern __shared__ float4 tab[];        // [NINT][256] swizzled

    const int gtid = blockIdx.x * EV_BLK + threadIdx.x;
    const int S    = EV_GRID * EV_BLK;     // float4 stride; multiple of 64

    // ---- prefetch first y batch (independent of the build kernel) ----
    int idx = gtid;
    float4 cur;
    if (idx < n4) cur = y4[idx];

    // ---- wait for build kernel's writes to be visible (PDL) ----
    cudaGridDependencySynchronize();

    // ---- assemble coefficients from the point table into swizzled smem ----
#pragma unroll
    for (int t = threadIdx.x; t < TAB_F4; t += EV_BLK) {
        const int ivp = t >> 8;                    // 0..15
        const int lp  = t & (LATENTS - 1);
        const float2 p0 = g_pts[ivp * LATENTS + lp];
        const float2 p1 = g_pts[(ivp + 1) * LATENTS + lp];
        float4 c;
        c.x = p0.x;
        c.y = p0.y;
        c.z = 3.0f * (p1.x - p0.x) - 2.0f * p0.y - p1.y;
        c.w = 2.0f * (p0.x - p1.x) + p0.y + p1.y;
        tab[ivp * LATENTS + (lp & 3) * 64 + (lp >> 2)] = c;
    }
    __syncthreads();

    // ---- stream y -> out ----
    const int lg = gtid & 63;              // latent group (4 latents)
    const float4* c0 = tab + lg;
    const float4* c1 = tab + lg + 64;
    const float4* c2 = tab + lg + 128;
    const float4* c3 = tab + lg + 192;

    while (idx < n4) {
        const int nidx = idx + S;
        float4 nxt;
        if (nidx < n4) nxt = y4[nidx];     // prefetch next batch

        float4 r;
        r.x = interp1(cur.x, c0);
        r.y = interp1(cur.y, c1);
        r.z = interp1(cur.z, c2);
        r.w = interp1(cur.w, c3);
        out4[idx] = r;

        cur = nxt;
        idx = nidx;
    }
}

extern "C" void kernel_launch(void* const* d_in, const int* in_sizes, int n_in,
                              void* d_out, int out_size)
{
    // metadata order: t, y, W1, b1, W2, b2, args
    const float* y  = (const float*)d_in[1];
    const float* W1 = (const float*)d_in[2];
    const float* b1 = (const float*)d_in[3];
    const float* W2 = (const float*)d_in[4];
    const float* b2 = (const float*)d_in[5];
    float* out = (float*)d_out;

    const int total = in_sizes[1];         // B*L = 4,194,304 (multiple of 4)
    const int n4 = total / 4;

    static int smem_set = 0;
    const int smem_bytes = TAB_F4 * (int)sizeof(float4);   // 65536
    if (!smem_set) {
        cudaFuncSetAttribute(eval_vec_kernel,
                             cudaFuncAttributeMaxDynamicSharedMemorySize,
                             smem_bytes);
        smem_set = 1;
    }

    // Primary kernel (legacy default stream, same as <<< >>>).
    build_pts_kernel<<<NPTS, LATENTS>>>(W1, b1, W2, b2);

    // Secondary kernel with Programmatic Dependent Launch: may begin
    // launching while the primary runs; correctness is guaranteed by
    // cudaGridDependencySynchronize() inside the kernel.
    cudaLaunchConfig_t cfg = {};
    cfg.gridDim  = dim3(EV_GRID, 1, 1);
    cfg.blockDim = dim3(EV_BLK, 1, 1);
    cfg.dynamicSmemBytes = smem_bytes;
    cfg.stream = 0;                        // legacy default stream
    cudaLaunchAttribute attrs[1];
    attrs[0].id = cudaLaunchAttributeProgrammaticStreamSerialization;
    attrs[0].val.programmaticStreamSerializationAllowed = 1;
    cfg.attrs = attrs;
    cfg.numAttrs = 1;

    cudaLaunchKernelEx(&cfg, eval_vec_kernel,
                       (const float4*)y, (float4*)out, n4);
}

// round 12
// speedup vs baseline: 1.3669x; 1.3669x over previous
#include <cuda_runtime.h>
#include <cuda_bf16.h>
#include <math.h>

// B=16384 samples, L=256 latents, H=16 hidden.
// out[b,l] = sigmoid( sum_h W2[l,h]*softplus(y[b,l]*W1[l,h]+b1[l,h]) + b2[l] )
//
// Single fused kernel, asymmetric producer/consumer:
//  CTAs 0..16 (first-launched): build grid point bid (256 latent point-evals),
//    publish to g_pts, bump g_built.
//  All CTAs: poll g_built (usually already satisfied), assemble per-interval
//    cubic coefficients into swizzled smem, stream y->out via LDS.128.

#define LATENTS 256
#define HID     16
#define NINT    16
#define NPTS    (NINT + 1)
#define Y_LO    (-6.5f)
#define STEP_F  (13.0f / (float)NINT)
#define INVH_F  ((float)NINT / 13.0f)
#define OFF_F   8.0f                       // -Y_LO * INVH

#define EV_GRID  296
#define EV_BLK   1024
#define TAB_F4   (NINT * LATENTS)          // 4096 float4 = 65536 B

// Global scratch (allocation-free). Counters are monotonic => graph-replay safe.
__device__ float2 g_pts[NPTS * LATENTS];
__device__ unsigned long long g_ticket = 0;  // +296 per launch
__device__ unsigned long long g_built  = 0;  // +17  per launch

// MLP value + step-scaled derivative at grid point pt, latent l.
__device__ __forceinline__ float2 mlp_point(int pt, int l,
                                            const float* __restrict__ W1,
                                            const float* __restrict__ b1,
                                            const float* __restrict__ W2,
                                            const float* __restrict__ b2)
{
    const float y0 = Y_LO + STEP_F * (float)pt;
    float a  = b2[l];
    float da = 0.0f;
#pragma unroll
    for (int h = 0; h < HID; ++h) {
        const float w1 = W1[l * HID + h];
        const float bb = b1[l * HID + h];
        const float w2 = W2[l * HID + h];
        const float x  = fmaf(y0, w1, bb);
        const float e  = __expf(-fabsf(x));                  // exp(-|x|) <= 1
        const float iv = __fdividef(1.0f, 1.0f + e);
        const float sp = fmaxf(x, 0.0f) + __logf(1.0f + e);  // softplus(x)
        const float s  = (x >= 0.0f) ? iv : e * iv;          // sigmoid(x)
        a  = fmaf(w2, sp, a);
        da = fmaf(w2 * s, w1, da);
    }
    const float eo = __expf(-a);
    const float g  = __fdividef(1.0f, 1.0f + eo);
    return make_float2(g, STEP_F * (g * (1.0f - g) * da));
}

__device__ __forceinline__ float interp1(float yv, const float4* __restrict__ col)
{
    float t = fmaf(yv, INVH_F, OFF_F);
    t = fminf(fmaxf(t, 0.0f), (float)NINT - 5e-4f);
    const int   i = (int)t;
    const float u = t - (float)i;
    const float4 c = col[i * LATENTS];     // stride 4096B per interval
    return fmaf(fmaf(fmaf(c.w, u, c.z), u, c.y), u, c.x);
}

__global__ __launch_bounds__(EV_BLK, 2)
void fused_kernel(const float4* __restrict__ y4,
                  float4* __restrict__ out4,
                  const float* __restrict__ W1,
                  const float* __restrict__ b1,
                  const float* __restrict__ W2,
                  const float* __restrict__ b2,
                  int n4)
{
    extern __shared__ float4 tab[];        // [NINT][256] swizzled

    const int gtid = blockIdx.x * EV_BLK + threadIdx.x;
    const int S    = EV_GRID * EV_BLK;     // float4 stride; multiple of 64

    // ---- prefetch first y batch (independent of the table) ----
    int idx = gtid;
    float4 cur;
    if (idx < n4) cur = y4[idx];

    // ---- producers: CTAs 0..16 build their grid point ----
    if (blockIdx.x < NPTS) {
        if (threadIdx.x < LATENTS)
            g_pts[blockIdx.x * LATENTS + threadIdx.x] =
                mlp_point(blockIdx.x, threadIdx.x, W1, b1, W2, b2);
        __syncthreads();
        if (threadIdx.x == 0) {
            __threadfence();               // release g_pts writes
            atomicAdd(&g_built, 1ULL);
        }
    }

    // ---- wait until all 17 producers of THIS launch have published ----
    if (threadIdx.x == 0) {
        const unsigned long long ticket = atomicAdd(&g_ticket, 1ULL);
        const unsigned long long target =
            (ticket / (unsigned long long)EV_GRID + 1ULL) * (unsigned long long)NPTS;
        while (*((volatile unsigned long long*)&g_built) < target)
            __nanosleep(64);
    }
    __syncthreads();
    __threadfence();                       // acquire: g_pts reads after the spin

    // ---- assemble coefficients into swizzled smem ----
#pragma unroll
    for (int t = threadIdx.x; t < TAB_F4; t += EV_BLK) {
        const int ivp = t >> 8;                    // 0..15
        const int lp  = t & (LATENTS - 1);
        const float2 p0 = g_pts[ivp * LATENTS + lp];
        const float2 p1 = g_pts[(ivp + 1) * LATENTS + lp];
        float4 c;
        c.x = p0.x;
        c.y = p0.y;
        c.z = 3.0f * (p1.x - p0.x) - 2.0f * p0.y - p1.y;
        c.w = 2.0f * (p0.x - p1.x) + p0.y + p1.y;
        tab[ivp * LATENTS + (lp & 3) * 64 + (lp >> 2)] = c;
    }
    __syncthreads();

    // ---- stream y -> out ----
    // Thread handles latents l = 4*lg+j (lg = gtid & 63); per-j LDS.128 is
    // stride-16B across lanes (conflict-free); iv adds multiples of 4096B.
    const int lg = gtid & 63;
    const float4* c0 = tab + lg;
    const float4* c1 = tab + lg + 64;
    const float4* c2 = tab + lg + 128;
    const float4* c3 = tab + lg + 192;

    while (idx < n4) {
        const int nidx = idx + S;
        float4 nxt;
        if (nidx < n4) nxt = y4[nidx];     // prefetch next batch

        float4 r;
        r.x = interp1(cur.x, c0);
        r.y = interp1(cur.y, c1);
        r.z = interp1(cur.z, c2);
        r.w = interp1(cur.w, c3);
        out4[idx] = r;

        cur = nxt;
        idx = nidx;
    }
}

extern "C" void kernel_launch(void* const* d_in, const int* in_sizes, int n_in,
                              void* d_out, int out_size)
{
    // metadata order: t, y, W1, b1, W2, b2, args
    const float* y  = (const float*)d_in[1];
    const float* W1 = (const float*)d_in[2];
    const float* b1 = (const float*)d_in[3];
    const float* W2 = (const float*)d_in[4];
    const float* b2 = (const float*)d_in[5];
    float* out = (float*)d_out;

    const int total = in_sizes[1];         // B*L = 4,194,304 (multiple of 4)
    const int n4 = total / 4;

    static int smem_set = 0;
    const int smem_bytes = TAB_F4 * (int)sizeof(float4);   // 65536
    if (!smem_set) {
        cudaFuncSetAttribute(fused_kernel,
                             cudaFuncAttributeMaxDynamicSharedMemorySize,
                             smem_bytes);
        smem_set = 1;
    }

    fused_kernel<<<EV_GRID, EV_BLK, smem_bytes>>>(
        (const float4*)y, (float4*)out, W1, b1, W2, b2, n4);
}

// round 13
// speedup vs baseline: 1.8020x; 1.3183x over previous
#include <cuda_runtime.h>
#include <cuda_bf16.h>
#include <math.h>

// B=16384 samples, L=256 latents, H=16 hidden.
// out[b,l] = sigmoid( sum_h W2[l,h]*softplus(y[b,l]*W1[l,h]+b1[l,h]) + b2[l] )
//
// Single fused kernel, 148 CTAs x 1024 threads (1 CTA/SM, 64 regs/thread):
//  CTAs 0..16: build grid point bid with h-parallel threads (4 thr/latent,
//    shfl reduce), publish to g_pts, bump g_built.
//  All CTAs: prefetch 4 y batches, poll g_built, assemble per-interval cubic
//    coefficients into swizzled smem, stream y->out 4 batches in flight.

#define LATENTS 256
#define HID     16
#define NINT    16
#define NPTS    (NINT + 1)
#define Y_LO    (-6.5f)
#define STEP_F  (13.0f / (float)NINT)
#define INVH_F  ((float)NINT / 13.0f)
#define OFF_F   8.0f                       // -Y_LO * INVH

#define EV_GRID  148
#define EV_BLK   1024
#define TAB_F4   (NINT * LATENTS)          // 4096 float4 = 65536 B

// Global scratch (allocation-free). Counters are monotonic => replay-safe.
__device__ float2 g_pts[NPTS * LATENTS];
__device__ unsigned long long g_ticket = 0;  // +148 per launch
__device__ unsigned long long g_built  = 0;  // +17  per launch

__device__ __forceinline__ float interp1(float yv, const float4* __restrict__ col)
{
    float t = fmaf(yv, INVH_F, OFF_F);
    t = fminf(fmaxf(t, 0.0f), (float)NINT - 5e-4f);   // fmaxf eats NaN from
    const int   i = (int)t;                            // garbage lanes safely
    const float u = t - (float)i;
    const float4 c = col[i * LATENTS];     // stride 4096B per interval
    return fmaf(fmaf(fmaf(c.w, u, c.z), u, c.y), u, c.x);
}

__global__ __launch_bounds__(EV_BLK, 1)
void fused_kernel(const float4* __restrict__ y4,
                  float4* __restrict__ out4,
                  const float* __restrict__ W1,
                  const float* __restrict__ b1,
                  const float* __restrict__ W2,
                  const float* __restrict__ b2,
                  int n4)
{
    extern __shared__ float4 tab[];        // [NINT][256] swizzled

    const int gtid = blockIdx.x * EV_BLK + threadIdx.x;
    const int S    = EV_GRID * EV_BLK;     // 151552 float4s; multiple of 64

    // ---- producers first: CTAs 0..16 build grid point = blockIdx.x ----
    // 4 threads per latent, 4 h-terms each, reduce via shfl_xor over lanes.
    if (blockIdx.x < NPTS) {
        const int l = threadIdx.x >> 2;            // 0..255
        const int q = threadIdx.x & 3;             // h-quarter
        const float y0 = Y_LO + STEP_F * (float)blockIdx.x;

        float a  = (q == 0) ? b2[l] : 0.0f;
        float da = 0.0f;
#pragma unroll
        for (int k = 0; k < 4; ++k) {
            const int h = q * 4 + k;
            const float w1 = W1[l * HID + h];
            const float bb = b1[l * HID + h];
            const float w2 = W2[l * HID + h];
            const float x  = fmaf(y0, w1, bb);
            const float e  = __expf(-fabsf(x));                 // <= 1
            const float iv = __fdividef(1.0f, 1.0f + e);
            const float sp = fmaxf(x, 0.0f) + __logf(1.0f + e); // softplus
            const float s  = (x >= 0.0f) ? iv : e * iv;         // sigmoid
            a  = fmaf(w2, sp, a);
            da = fmaf(w2 * s, w1, da);
        }
        a  += __shfl_xor_sync(0xffffffffu, a, 1);
        da += __shfl_xor_sync(0xffffffffu, da, 1);
        a  += __shfl_xor_sync(0xffffffffu, a, 2);
        da += __shfl_xor_sync(0xffffffffu, da, 2);
        if (q == 0) {
            const float eo = __expf(-a);
            const float g  = __fdividef(1.0f, 1.0f + eo);
            g_pts[blockIdx.x * LATENTS + l] =
                make_float2(g, STEP_F * (g * (1.0f - g) * da));
        }
        __syncthreads();
        if (threadIdx.x == 0) {
            __threadfence();               // release g_pts writes
            atomicAdd(&g_built, 1ULL);
        }
    }

    // ---- prefetch 4 y batches (independent of the table) ----
    int base = gtid;
    const float4 z = make_float4(0.f, 0.f, 0.f, 0.f);
    float4 a0 = (base          < n4) ? y4[base]         : z;
    float4 a1 = (base + S      < n4) ? y4[base + S]     : z;
    float4 a2 = (base + 2 * S  < n4) ? y4[base + 2 * S] : z;
    float4 a3 = (base + 3 * S  < n4) ? y4[base + 3 * S] : z;

    // ---- wait until all 17 producers of THIS launch have published ----
    if (threadIdx.x == 0) {
        const unsigned long long ticket = atomicAdd(&g_ticket, 1ULL);
        const unsigned long long target =
            (ticket / (unsigned long long)EV_GRID + 1ULL) * (unsigned long long)NPTS;
        while (*((volatile unsigned long long*)&g_built) < target)
            __nanosleep(32);
    }
    __syncthreads();
    __threadfence();                       // acquire: g_pts reads after spin

    // ---- assemble coefficients into swizzled smem ----
#pragma unroll
    for (int t = threadIdx.x; t < TAB_F4; t += EV_BLK) {
        const int ivp = t >> 8;                    // 0..15
        const int lp  = t & (LATENTS - 1);
        const float2 p0 = g_pts[ivp * LATENTS + lp];
        const float2 p1 = g_pts[(ivp + 1) * LATENTS + lp];
        float4 c;
        c.x = p0.x;
        c.y = p0.y;
        c.z = 3.0f * (p1.x - p0.x) - 2.0f * p0.y - p1.y;
        c.w = 2.0f * (p0.x - p1.x) + p0.y + p1.y;
        tab[ivp * LATENTS + (lp & 3) * 64 + (lp >> 2)] = c;
    }
    __syncthreads();

    // ---- stream y -> out, 4 batches in flight ----
    // Thread handles latents l = 4*lg+j (lg = gtid & 63); per-j LDS.128 is
    // stride-16B across lanes (conflict-free); iv adds multiples of 4096B.
    const int lg = gtid & 63;
    const float4* c0 = tab + lg;
    const float4* c1 = tab + lg + 64;
    const float4* c2 = tab + lg + 128;
    const float4* c3 = tab + lg + 192;

    while (base < n4) {
        const int nb = base + 4 * S;
        float4 b0 = (nb          < n4) ? y4[nb]         : z;
        float4 b1v = (nb + S     < n4) ? y4[nb + S]     : z;
        float4 b2v = (nb + 2 * S < n4) ? y4[nb + 2 * S] : z;
        float4 b3 = (nb + 3 * S  < n4) ? y4[nb + 3 * S] : z;

        float4 r0, r1, r2, r3;
        r0.x = interp1(a0.x, c0); r0.y = interp1(a0.y, c1);
        r0.z = interp1(a0.z, c2); r0.w = interp1(a0.w, c3);
        r1.x = interp1(a1.x, c0); r1.y = interp1(a1.y, c1);
        r1.z = interp1(a1.z, c2); r1.w = interp1(a1.w, c3);
        r2.x = interp1(a2.x, c0); r2.y = interp1(a2.y, c1);
        r2.z = interp1(a2.z, c2); r2.w = interp1(a2.w, c3);
        r3.x = interp1(a3.x, c0); r3.y = interp1(a3.y, c1);
        r3.z = interp1(a3.z, c2); r3.w = interp1(a3.w, c3);

        out4[base] = r0;
        if (base + S     < n4) out4[base + S]     = r1;
        if (base + 2 * S < n4) out4[base + 2 * S] = r2;
        if (base + 3 * S < n4) out4[base + 3 * S] = r3;

        a0 = b0; a1 = b1v; a2 = b2v; a3 = b3;
        base = nb;
    }
}

extern "C" void kernel_launch(void* const* d_in, const int* in_sizes, int n_in,
                              void* d_out, int out_size)
{
    // metadata order: t, y, W1, b1, W2, b2, args
    const float* y  = (const float*)d_in[1];
    const float* W1 = (const float*)d_in[2];
    const float* b1 = (const float*)d_in[3];
    const float* W2 = (const float*)d_in[4];
    const float* b2 = (const float*)d_in[5];
    float* out = (float*)d_out;

    const int total = in_sizes[1];         // B*L = 4,194,304 (multiple of 4)
    const int n4 = total / 4;

    static int smem_set = 0;
    const int smem_bytes = TAB_F4 * (int)sizeof(float4);   // 65536
    if (!smem_set) {
        cudaFuncSetAttribute(fused_kernel,
                             cudaFuncAttributeMaxDynamicSharedMemorySize,
                             smem_bytes);
        smem_set = 1;
    }

    fused_kernel<<<EV_GRID, EV_BLK, smem_bytes>>>(
        (const float4*)y, (float4*)out, W1, b1, W2, b2, n4);
}